// round 3
// baseline (speedup 1.0000x reference)
#include <cuda_runtime.h>
#include <cstdint>

// Problem constants
#define Bb 32
#define Np 2048
#define NSd 512
#define KN 16
#define NT (Bb*NSd)          // 16384 tiles (b,ns)
#define JJ (NT*KN)           // 262144 columns
#define EPSf 1e-5

// ---------------- scratch (static __device__, no allocs) ----------------
__device__ float  g_grouped[NT*KN*3];          // 3 MB  grouped coords [tile][k][3]
__device__ double g_sum9[9];                   // Sg(3) + Sgg(6)
__device__ float  g_Weff2[256*3];
__device__ float  g_W3T[512*512];              // [c][o]
__device__ float  g_W4T[512*256];              // [c][o]
__device__ float  g_A1[256*3];
__device__ float  g_c1v[256];
__device__ float  g_H [256u*JJ];               // 268 MB  h (post BN1+ReLU) [c][j]
__device__ float  g_P [256u*NT];               // pooled [c][tile]
__device__ float  g_Zp[512u*NT];               // W3a @ pooled [o][tile]
__device__ float  g_Z [512u*JJ];               // 537 MB
__device__ float  g_Z4[256u*JJ];               // 268 MB
__device__ double g_bn3sum[512], g_bn3sq[512], g_bn4sum[256], g_bn4sq[256];
__device__ float  g_a3[512], g_d3[512], g_a4[256], g_d4[256];

// ---------------- zero accumulators (graph replays!) ----------------
__global__ void zerok() {
    int t = threadIdx.x;
    if (t < 9) g_sum9[t] = 0.0;
    for (int i = t; i < 512; i += blockDim.x) { g_bn3sum[i] = 0.0; g_bn3sq[i] = 0.0; }
    for (int i = t; i < 256; i += blockDim.x) { g_bn4sum[i] = 0.0; g_bn4sq[i] = 0.0; }
}

// ---------------- precompute Weff2 = W2 @ (w1[:, :3]+w1[:,3:]), transposes ----------------
__global__ void precompk(const float* __restrict__ w1, const float* __restrict__ w2,
                         const float* __restrict__ w3, const float* __restrict__ w4) {
    int t = threadIdx.x;
    if (t < 256) {
        double s0 = 0.0, s1 = 0.0, s2 = 0.0;
        for (int i = 0; i < 256; i++) {
            double wi = (double)w2[t*256 + i];
            s0 += wi * ((double)w1[i*6+0] + (double)w1[i*6+3]);
            s1 += wi * ((double)w1[i*6+1] + (double)w1[i*6+4]);
            s2 += wi * ((double)w1[i*6+2] + (double)w1[i*6+5]);
        }
        g_Weff2[t*3+0] = (float)s0; g_Weff2[t*3+1] = (float)s1; g_Weff2[t*3+2] = (float)s2;
    }
    for (int idx = t; idx < 512*512; idx += blockDim.x) {
        int o = idx >> 9, c = idx & 511;
        g_W3T[c*512 + o] = w3[idx];
    }
    for (int idx = t; idx < 256*512; idx += blockDim.x) {
        int o = idx >> 9, c = idx & 511;
        g_W4T[c*256 + o] = w4[idx];
    }
}

// ---------------- FPS: 32 blocks (one per batch), 512 threads, 4 pts/thread ----------------
__global__ void fpsk(const float* __restrict__ p, float* __restrict__ outc) {
    __shared__ float sp[Np*3];
    __shared__ unsigned long long skey[16];
    __shared__ int s_cs;
    int b = blockIdx.x, t = threadIdx.x;
    for (int i = t; i < Np*3; i += 512) sp[i] = p[b*Np*3 + i];
    __syncthreads();

    float px[4], py[4], pz[4], dist[4];
    #pragma unroll
    for (int i = 0; i < 4; i++) {
        int n = t + 512*i;
        px[i] = sp[n*3+0]; py[i] = sp[n*3+1]; pz[i] = sp[n*3+2];
        dist[i] = 1e10f;
    }
    int lane = t & 31, wid = t >> 5;
    int cs = 0;
    for (int s = 0; s < NSd; s++) {
        if (t == 0) {
            outc[(b*NSd + s)*3 + 0] = sp[cs*3+0];
            outc[(b*NSd + s)*3 + 1] = sp[cs*3+1];
            outc[(b*NSd + s)*3 + 2] = sp[cs*3+2];
        }
        float cx = sp[cs*3+0], cy = sp[cs*3+1], cz = sp[cs*3+2];
        unsigned long long best = 0ull;
        #pragma unroll
        for (int i = 0; i < 4; i++) {
            float dx = __fadd_rn(px[i], -cx);
            float dy = __fadd_rn(py[i], -cy);
            float dz = __fadd_rn(pz[i], -cz);
            float d = __fadd_rn(__fadd_rn(__fmul_rn(dx,dx), __fmul_rn(dy,dy)), __fmul_rn(dz,dz));
            dist[i] = fminf(dist[i], d);
            unsigned long long key = ((unsigned long long)__float_as_uint(dist[i]) << 32)
                                   | (unsigned)(Np - 1 - (t + 512*i));
            best = max(best, key);
        }
        #pragma unroll
        for (int off = 16; off; off >>= 1)
            best = max(best, __shfl_down_sync(0xffffffffu, best, off));
        if (lane == 0) skey[wid] = best;
        __syncthreads();
        if (t < 16) {
            unsigned long long k2 = skey[t];
            #pragma unroll
            for (int off = 8; off; off >>= 1)
                k2 = max(k2, __shfl_down_sync(0xffffu, k2, off));
            if (t == 0) s_cs = Np - 1 - (int)(unsigned)(k2 & 0xffffffffull);
        }
        __syncthreads();
        cs = s_cs;
    }
}

// ---------------- kNN: 64 blocks x 256 threads, 1 centroid/thread ----------------
__global__ void knnk(const float* __restrict__ p, const float* __restrict__ cntrd) {
    __shared__ float shp[Np*3];
    __shared__ float sp2[Np];
    __shared__ double s9[9];
    int t = threadIdx.x;
    int gc = blockIdx.x*256 + t;           // global centroid
    int b = blockIdx.x >> 1;               // 2 blocks per batch
    for (int i = t; i < Np*3; i += 256) shp[i] = p[b*Np*3 + i];
    if (t < 9) s9[t] = 0.0;
    __syncthreads();
    for (int n = t; n < Np; n += 256) {
        float x = shp[n*3], y = shp[n*3+1], z = shp[n*3+2];
        sp2[n] = __fadd_rn(__fadd_rn(__fmul_rn(x,x), __fmul_rn(y,y)), __fmul_rn(z,z));
    }
    __syncthreads();

    float cx = cntrd[gc*3+0], cy = cntrd[gc*3+1], cz = cntrd[gc*3+2];
    float c2 = __fadd_rn(__fadd_rn(__fmul_rn(cx,cx), __fmul_rn(cy,cy)), __fmul_rn(cz,cz));

    float hd[KN]; int hi[KN];
    #pragma unroll
    for (int k = 0; k < KN; k++) { hd[k] = 3.4e38f; hi[k] = 0; }

    for (int n = 0; n < Np; n++) {
        float dot = __fadd_rn(__fadd_rn(__fmul_rn(cx, shp[n*3]),
                                        __fmul_rn(cy, shp[n*3+1])),
                              __fmul_rn(cz, shp[n*3+2]));
        float d2 = __fadd_rn(__fadd_rn(c2, sp2[n]), -__fmul_rn(2.0f, dot));
        if (d2 < hd[KN-1]) {
            hd[KN-1] = d2; hi[KN-1] = n;
            #pragma unroll
            for (int j = KN-1; j > 0; --j) {
                bool sw = hd[j] < hd[j-1];
                float td = hd[j]; int ti = hi[j];
                float tdm = hd[j-1]; int tim = hi[j-1];
                hd[j]   = sw ? tdm : td;   hi[j]   = sw ? tim : ti;
                hd[j-1] = sw ? td  : tdm;  hi[j-1] = sw ? ti  : tim;
            }
        }
    }
    double sx=0, sy=0, sz=0, sxx=0, syy=0, szz=0, sxy=0, sxz=0, syz=0;
    #pragma unroll
    for (int k = 0; k < KN; k++) {
        int n = hi[k];
        float x = shp[n*3], y = shp[n*3+1], z = shp[n*3+2];
        g_grouped[(gc*KN + k)*3 + 0] = x;
        g_grouped[(gc*KN + k)*3 + 1] = y;
        g_grouped[(gc*KN + k)*3 + 2] = z;
        sx += x; sy += y; sz += z;
        sxx += (double)x*x; syy += (double)y*y; szz += (double)z*z;
        sxy += (double)x*y; sxz += (double)x*z; syz += (double)y*z;
    }
    atomicAdd(&s9[0], sx);  atomicAdd(&s9[1], sy);  atomicAdd(&s9[2], sz);
    atomicAdd(&s9[3], sxx); atomicAdd(&s9[4], syy); atomicAdd(&s9[5], szz);
    atomicAdd(&s9[6], sxy); atomicAdd(&s9[7], sxz); atomicAdd(&s9[8], syz);
    __syncthreads();
    if (t < 9) atomicAdd(&g_sum9[t], s9[t]);
}

// ---------------- BN1 affine from analytic moments ----------------
__global__ void bn1k(const float* __restrict__ b2, const float* __restrict__ g1,
                     const float* __restrict__ b1) {
    int o = threadIdx.x;
    if (o >= 256) return;
    double inv = 1.0 / (double)JJ;
    double Ex = g_sum9[0]*inv, Ey = g_sum9[1]*inv, Ez = g_sum9[2]*inv;
    double Mxx = g_sum9[3]*inv, Myy = g_sum9[4]*inv, Mzz = g_sum9[5]*inv;
    double Mxy = g_sum9[6]*inv, Mxz = g_sum9[7]*inv, Myz = g_sum9[8]*inv;
    double w0 = g_Weff2[o*3], w1v = g_Weff2[o*3+1], w2v = g_Weff2[o*3+2];
    double bo = b2[o];
    double wEg = w0*Ex + w1v*Ey + w2v*Ez;
    double m = wEg + bo;
    double Ex2 = w0*w0*Mxx + w1v*w1v*Myy + w2v*w2v*Mzz
               + 2.0*(w0*w1v*Mxy + w0*w2v*Mxz + w1v*w2v*Myz)
               + 2.0*bo*wEg + bo*bo;
    double var = Ex2 - m*m;
    double s = (double)g1[o] / sqrt(var + EPSf);
    g_A1[o*3+0] = (float)(s*w0);
    g_A1[o*3+1] = (float)(s*w1v);
    g_A1[o*3+2] = (float)(s*w2v);
    g_c1v[o] = (float)((double)b1[o] + s*(bo - m));
}

// ---------------- h generation + pooled ----------------
__global__ void hgenk() {
    __shared__ float gsh[48];
    int t = threadIdx.x;
    float a0 = g_A1[t*3], a1 = g_A1[t*3+1], a2 = g_A1[t*3+2], c1 = g_c1v[t];
    for (int it = 0; it < 8; it++) {
        int tile = blockIdx.x*8 + it;
        __syncthreads();
        if (t < 48) gsh[t] = g_grouped[tile*48 + t];
        __syncthreads();
        float hv[KN];
        float mx = 0.0f;
        #pragma unroll
        for (int k = 0; k < KN; k++) {
            float x = gsh[k*3], y = gsh[k*3+1], z = gsh[k*3+2];
            float h = fmaxf(0.0f, fmaf(a0, x, fmaf(a1, y, fmaf(a2, z, c1))));
            hv[k] = h;
            mx = fmaxf(mx, h);
        }
        float* dst = &g_H[(size_t)t*JJ + (size_t)tile*KN];
        #pragma unroll
        for (int q = 0; q < 4; q++)
            *(float4*)(dst + 4*q) = make_float4(hv[4*q], hv[4*q+1], hv[4*q+2], hv[4*q+3]);
        g_P[(size_t)t*NT + tile] = mx;
    }
}

// ---------------- generic 128x128 tiled GEMM, fused epilogues ----------------
// MODE 0: C = AT^T B                      (Zp)
// MODE 1: C = AT^T B + zp[o][j>>4], stats (Z, BN3)
// MODE 2: C = AT^T relu(a*B+d), stats     (Z4, BN4)
template<int MODE>
__global__ __launch_bounds__(256, 2)
void gemm128(const float* __restrict__ AT, int M,
             const float* __restrict__ Bm, int Nn,
             float* __restrict__ Cm, int Kdim,
             const float* __restrict__ zp,
             const float* __restrict__ ta, const float* __restrict__ tb,
             double* __restrict__ sumo, double* __restrict__ sqo) {
    __shared__ float As[2][8][128];
    __shared__ float Bs[2][8][128];
    __shared__ double shs[128], shq[128];
    int t = threadIdx.x;
    int tx = t & 15, ty = t >> 4;
    int o0 = blockIdx.y * 128, j0 = blockIdx.x * 128;
    int lk = t >> 5;            // 0..7
    int lo = (t & 31) * 4;      // 0..124

    float acc[8][8];
    #pragma unroll
    for (int r = 0; r < 8; r++)
        #pragma unroll
        for (int c = 0; c < 8; c++) acc[r][c] = 0.0f;

    // stage 0
    {
        float4 va = *(const float4*)&AT[(size_t)lk*M + o0 + lo];
        float4 vb = *(const float4*)&Bm[(size_t)lk*Nn + j0 + lo];
        if (MODE == 2) {
            float a = ta[lk], d = tb[lk];
            vb.x = fmaxf(0.0f, fmaf(vb.x, a, d));
            vb.y = fmaxf(0.0f, fmaf(vb.y, a, d));
            vb.z = fmaxf(0.0f, fmaf(vb.z, a, d));
            vb.w = fmaxf(0.0f, fmaf(vb.w, a, d));
        }
        *(float4*)&As[0][lk][lo] = va;
        *(float4*)&Bs[0][lk][lo] = vb;
    }
    __syncthreads();

    int cur = 0;
    for (int kc = 0; kc < Kdim; kc += 8) {
        bool has = (kc + 8) < Kdim;
        float4 ra, rb;
        if (has) {
            ra = *(const float4*)&AT[(size_t)(kc + 8 + lk)*M + o0 + lo];
            rb = *(const float4*)&Bm[(size_t)(kc + 8 + lk)*Nn + j0 + lo];
            if (MODE == 2) {
                float a = ta[kc + 8 + lk], d = tb[kc + 8 + lk];
                rb.x = fmaxf(0.0f, fmaf(rb.x, a, d));
                rb.y = fmaxf(0.0f, fmaf(rb.y, a, d));
                rb.z = fmaxf(0.0f, fmaf(rb.z, a, d));
                rb.w = fmaxf(0.0f, fmaf(rb.w, a, d));
            }
        }
        #pragma unroll
        for (int kk = 0; kk < 8; kk++) {
            float av[8], bv[8];
            *(float4*)&av[0] = *(float4*)&As[cur][kk][ty*8];
            *(float4*)&av[4] = *(float4*)&As[cur][kk][ty*8 + 4];
            *(float4*)&bv[0] = *(float4*)&Bs[cur][kk][tx*8];
            *(float4*)&bv[4] = *(float4*)&Bs[cur][kk][tx*8 + 4];
            #pragma unroll
            for (int r = 0; r < 8; r++)
                #pragma unroll
                for (int c = 0; c < 8; c++)
                    acc[r][c] = fmaf(av[r], bv[c], acc[r][c]);
        }
        if (has) {
            *(float4*)&As[cur^1][lk][lo] = ra;
            *(float4*)&Bs[cur^1][lk][lo] = rb;
        }
        __syncthreads();
        cur ^= 1;
    }

    if (MODE == 0) {
        #pragma unroll
        for (int r = 0; r < 8; r++) {
            int o = o0 + ty*8 + r;
            float* cp = &Cm[(size_t)o*Nn + j0 + tx*8];
            *(float4*)cp       = make_float4(acc[r][0], acc[r][1], acc[r][2], acc[r][3]);
            *(float4*)(cp + 4) = make_float4(acc[r][4], acc[r][5], acc[r][6], acc[r][7]);
        }
    } else {
        double rs[8], rq[8];
        #pragma unroll
        for (int r = 0; r < 8; r++) { rs[r] = 0.0; rq[r] = 0.0; }
        #pragma unroll
        for (int r = 0; r < 8; r++) {
            int o = o0 + ty*8 + r;
            float vals[8];
            #pragma unroll
            for (int c = 0; c < 8; c++) {
                int j = j0 + tx*8 + c;
                float v = acc[r][c];
                if (MODE == 1) v += zp[(size_t)o*NT + (j >> 4)];
                vals[c] = v;
                rs[r] += (double)v;
                rq[r] += (double)v * (double)v;
            }
            float* cp = &Cm[(size_t)o*Nn + j0 + tx*8];
            *(float4*)cp       = make_float4(vals[0], vals[1], vals[2], vals[3]);
            *(float4*)(cp + 4) = make_float4(vals[4], vals[5], vals[6], vals[7]);
        }
        if (t < 128) { shs[t] = 0.0; shq[t] = 0.0; }
        __syncthreads();
        #pragma unroll
        for (int r = 0; r < 8; r++) {
            atomicAdd(&shs[ty*8 + r], rs[r]);
            atomicAdd(&shq[ty*8 + r], rq[r]);
        }
        __syncthreads();
        if (t < 128) {
            atomicAdd(&sumo[o0 + t], shs[t]);
            atomicAdd(&sqo[o0 + t], shq[t]);
        }
    }
}

// ---------------- BN affine param kernels ----------------
__global__ void bn3aff(const float* __restrict__ g, const float* __restrict__ b) {
    int c = threadIdx.x;
    if (c >= 512) return;
    double inv = 1.0 / (double)JJ;
    double m = g_bn3sum[c]*inv;
    double var = g_bn3sq[c]*inv - m*m;
    float a = (float)((double)g[c] / sqrt(var + EPSf));
    g_a3[c] = a;
    g_d3[c] = b[c] - (float)m * a;
}
__global__ void bn4aff(const float* __restrict__ g, const float* __restrict__ b) {
    int c = threadIdx.x;
    if (c >= 256) return;
    double inv = 1.0 / (double)JJ;
    double m = g_bn4sum[c]*inv;
    double var = g_bn4sq[c]*inv - m*m;
    float a = (float)((double)g[c] / sqrt(var + EPSf));
    g_a4[c] = a;
    g_d4[c] = b[c] - (float)m * a;
}

// ---------------- final: BN4 + ReLU + max over k -> feat ----------------
__global__ void finalk(float* __restrict__ out) {
    int id = blockIdx.x*256 + threadIdx.x;            // b*131072 + o*512 + ns
    int b = id >> 17;
    int o = (id >> 9) & 255;
    int ns = id & 511;
    float a = g_a4[o], d = g_d4[o];
    const float4* zr = (const float4*)&g_Z4[(size_t)o*JJ + (size_t)((b << 9) | ns)*KN];
    float mx = 0.0f;
    #pragma unroll
    for (int q = 0; q < 4; q++) {
        float4 v = zr[q];
        mx = fmaxf(mx, fmaxf(0.0f, fmaf(v.x, a, d)));
        mx = fmaxf(mx, fmaxf(0.0f, fmaf(v.y, a, d)));
        mx = fmaxf(mx, fmaxf(0.0f, fmaf(v.z, a, d)));
        mx = fmaxf(mx, fmaxf(0.0f, fmaf(v.w, a, d)));
    }
    out[Bb*NSd*3 + id] = mx;
}

// ---------------- launch ----------------
extern "C" void kernel_launch(void* const* d_in, const int* in_sizes, int n_in,
                              void* d_out, int out_size) {
    const float* p    = (const float*)d_in[0];
    const float* w1   = (const float*)d_in[1];
    const float* w2   = (const float*)d_in[2];
    const float* b2   = (const float*)d_in[3];
    const float* bn1g = (const float*)d_in[4];
    const float* bn1b = (const float*)d_in[5];
    const float* w3   = (const float*)d_in[6];
    const float* bn3g = (const float*)d_in[7];
    const float* bn3b = (const float*)d_in[8];
    const float* w4   = (const float*)d_in[9];
    const float* bn4g = (const float*)d_in[10];
    const float* bn4b = (const float*)d_in[11];
    float* out = (float*)d_out;

    float*  dH;  cudaGetSymbolAddress((void**)&dH,  g_H);
    float*  dP;  cudaGetSymbolAddress((void**)&dP,  g_P);
    float*  dZp; cudaGetSymbolAddress((void**)&dZp, g_Zp);
    float*  dZ;  cudaGetSymbolAddress((void**)&dZ,  g_Z);
    float*  dZ4; cudaGetSymbolAddress((void**)&dZ4, g_Z4);
    float*  dW3T; cudaGetSymbolAddress((void**)&dW3T, g_W3T);
    float*  dW4T; cudaGetSymbolAddress((void**)&dW4T, g_W4T);
    float*  da3; cudaGetSymbolAddress((void**)&da3, g_a3);
    float*  dd3; cudaGetSymbolAddress((void**)&dd3, g_d3);
    double* ds3; cudaGetSymbolAddress((void**)&ds3, g_bn3sum);
    double* dq3; cudaGetSymbolAddress((void**)&dq3, g_bn3sq);
    double* ds4; cudaGetSymbolAddress((void**)&ds4, g_bn4sum);
    double* dq4; cudaGetSymbolAddress((void**)&dq4, g_bn4sq);

    zerok<<<1, 512>>>();
    precompk<<<1, 512>>>(w1, w2, w3, w4);
    fpsk<<<32, 512>>>(p, out);                 // writes cntrd to out[0:49152]
    knnk<<<64, 256>>>(p, out);
    bn1k<<<1, 256>>>(b2, bn1g, bn1b);
    hgenk<<<NT/8, 256>>>();
    // Zp = W3a @ pooled : M=512, K=256, N=16384
    gemm128<0><<<dim3(NT/128, 4), 256>>>(dW3T, 512, dP, NT, dZp, 256,
                                         nullptr, nullptr, nullptr, nullptr, nullptr);
    // Z = W3b @ H + zp, BN3 stats : M=512, K=256, N=262144
    gemm128<1><<<dim3(JJ/128, 4), 256>>>(dW3T + 256*512, 512, dH, JJ, dZ, 256,
                                         dZp, nullptr, nullptr, ds3, dq3);
    bn3aff<<<1, 512>>>(bn3g, bn3b);
    // Z4 = W4 @ relu(bn3(Z)), BN4 stats : M=256, K=512, N=262144
    gemm128<2><<<dim3(JJ/128, 2), 256>>>(dW4T, 256, dZ, JJ, dZ4, 512,
                                         nullptr, da3, dd3, ds4, dq4);
    bn4aff<<<1, 256>>>(bn4g, bn4b);
    finalk<<<Bb*256*NSd/256, 256>>>(out);
}

// round 4
// speedup vs baseline: 1.0015x; 1.0015x over previous
#include <cuda_runtime.h>
#include <cstdint>

// Problem constants
#define Bb 32
#define Np 2048
#define NSd 512
#define KN 16
#define NT (Bb*NSd)          // 16384 tiles (b,ns)
#define JJ (NT*KN)           // 262144 columns
#define EPSf 1e-5

// ---------------- scratch (static __device__, no allocs) ----------------
__device__ float  g_grouped[NT*KN*3];          // 3 MB  grouped coords [tile][k][3]
__device__ double g_sum9[9];                   // Sg(3) + Sgg(6)
__device__ float  g_Weff2[256*3];
__device__ float  g_W3T[512*512];              // [c][o]
__device__ float  g_W4T[512*256];              // [c][o]
__device__ float  g_A1[256*3];
__device__ float  g_c1v[256];
__device__ float  g_H [256u*JJ];               // 268 MB  h (post BN1+ReLU) [c][j]
__device__ float  g_P [256u*NT];               // pooled [c][tile]
__device__ float  g_Zp[512u*NT];               // W3a @ pooled [o][tile]
__device__ float  g_Z [512u*JJ];               // 537 MB
__device__ float  g_Z4[256u*JJ];               // 268 MB
__device__ double g_bn3sum[512], g_bn3sq[512], g_bn4sum[256], g_bn4sq[256];
__device__ float  g_a3[512], g_d3[512], g_a4[256], g_d4[256];

// ---------------- zero accumulators (graph replays!) ----------------
__global__ void zerok() {
    int t = threadIdx.x;
    if (t < 9) g_sum9[t] = 0.0;
    for (int i = t; i < 512; i += blockDim.x) { g_bn3sum[i] = 0.0; g_bn3sq[i] = 0.0; }
    for (int i = t; i < 256; i += blockDim.x) { g_bn4sum[i] = 0.0; g_bn4sq[i] = 0.0; }
}

// ---------------- precompute Weff2 = W2 @ (w1[:, :3]+w1[:,3:]), transposes ----------------
__global__ void precompk(const float* __restrict__ w1, const float* __restrict__ w2,
                         const float* __restrict__ w3, const float* __restrict__ w4) {
    int t = threadIdx.x;
    if (t < 256) {
        double s0 = 0.0, s1 = 0.0, s2 = 0.0;
        for (int i = 0; i < 256; i++) {
            double wi = (double)w2[t*256 + i];
            s0 += wi * ((double)w1[i*6+0] + (double)w1[i*6+3]);
            s1 += wi * ((double)w1[i*6+1] + (double)w1[i*6+4]);
            s2 += wi * ((double)w1[i*6+2] + (double)w1[i*6+5]);
        }
        g_Weff2[t*3+0] = (float)s0; g_Weff2[t*3+1] = (float)s1; g_Weff2[t*3+2] = (float)s2;
    }
    for (int idx = t; idx < 512*512; idx += blockDim.x) {
        int o = idx >> 9, c = idx & 511;
        g_W3T[c*512 + o] = w3[idx];
    }
    for (int idx = t; idx < 256*512; idx += blockDim.x) {
        int o = idx >> 9, c = idx & 511;
        g_W4T[c*256 + o] = w4[idx];
    }
}

// ---------------- FPS: 32 blocks (one per batch), 512 threads, 4 pts/thread ----------------
__global__ void fpsk(const float* __restrict__ p, float* __restrict__ outc) {
    __shared__ float sp[Np*3];
    __shared__ unsigned long long skey[16];
    __shared__ int s_cs;
    int b = blockIdx.x, t = threadIdx.x;
    for (int i = t; i < Np*3; i += 512) sp[i] = p[b*Np*3 + i];
    __syncthreads();

    float px[4], py[4], pz[4], dist[4];
    #pragma unroll
    for (int i = 0; i < 4; i++) {
        int n = t + 512*i;
        px[i] = sp[n*3+0]; py[i] = sp[n*3+1]; pz[i] = sp[n*3+2];
        dist[i] = 1e10f;
    }
    int lane = t & 31, wid = t >> 5;
    int cs = 0;
    for (int s = 0; s < NSd; s++) {
        if (t == 0) {
            outc[(b*NSd + s)*3 + 0] = sp[cs*3+0];
            outc[(b*NSd + s)*3 + 1] = sp[cs*3+1];
            outc[(b*NSd + s)*3 + 2] = sp[cs*3+2];
        }
        float cx = sp[cs*3+0], cy = sp[cs*3+1], cz = sp[cs*3+2];
        unsigned long long best = 0ull;
        #pragma unroll
        for (int i = 0; i < 4; i++) {
            float dx = __fadd_rn(px[i], -cx);
            float dy = __fadd_rn(py[i], -cy);
            float dz = __fadd_rn(pz[i], -cz);
            float d = __fadd_rn(__fadd_rn(__fmul_rn(dx,dx), __fmul_rn(dy,dy)), __fmul_rn(dz,dz));
            dist[i] = fminf(dist[i], d);
            unsigned long long key = ((unsigned long long)__float_as_uint(dist[i]) << 32)
                                   | (unsigned)(Np - 1 - (t + 512*i));
            best = max(best, key);
        }
        #pragma unroll
        for (int off = 16; off; off >>= 1)
            best = max(best, __shfl_down_sync(0xffffffffu, best, off));
        if (lane == 0) skey[wid] = best;
        __syncthreads();
        if (t < 16) {
            unsigned long long k2 = skey[t];
            #pragma unroll
            for (int off = 8; off; off >>= 1)
                k2 = max(k2, __shfl_down_sync(0xffffu, k2, off));
            if (t == 0) s_cs = Np - 1 - (int)(unsigned)(k2 & 0xffffffffull);
        }
        __syncthreads();
        cs = s_cs;
    }
}

// ---------------- kNN: 64 blocks x 256 threads, 1 centroid/thread ----------------
__global__ void knnk(const float* __restrict__ p, const float* __restrict__ cntrd) {
    __shared__ float shp[Np*3];
    __shared__ float sp2[Np];
    __shared__ double s9[9];
    int t = threadIdx.x;
    int gc = blockIdx.x*256 + t;           // global centroid
    int b = blockIdx.x >> 1;               // 2 blocks per batch
    for (int i = t; i < Np*3; i += 256) shp[i] = p[b*Np*3 + i];
    if (t < 9) s9[t] = 0.0;
    __syncthreads();
    for (int n = t; n < Np; n += 256) {
        float x = shp[n*3], y = shp[n*3+1], z = shp[n*3+2];
        sp2[n] = __fadd_rn(__fadd_rn(__fmul_rn(x,x), __fmul_rn(y,y)), __fmul_rn(z,z));
    }
    __syncthreads();

    float cx = cntrd[gc*3+0], cy = cntrd[gc*3+1], cz = cntrd[gc*3+2];
    float c2 = __fadd_rn(__fadd_rn(__fmul_rn(cx,cx), __fmul_rn(cy,cy)), __fmul_rn(cz,cz));

    float hd[KN]; int hi[KN];
    #pragma unroll
    for (int k = 0; k < KN; k++) { hd[k] = 3.4e38f; hi[k] = 0; }

    for (int n = 0; n < Np; n++) {
        float dot = __fadd_rn(__fadd_rn(__fmul_rn(cx, shp[n*3]),
                                        __fmul_rn(cy, shp[n*3+1])),
                              __fmul_rn(cz, shp[n*3+2]));
        float d2 = __fadd_rn(__fadd_rn(c2, sp2[n]), -__fmul_rn(2.0f, dot));
        if (d2 < hd[KN-1]) {
            hd[KN-1] = d2; hi[KN-1] = n;
            #pragma unroll
            for (int j = KN-1; j > 0; --j) {
                bool sw = hd[j] < hd[j-1];
                float td = hd[j]; int ti = hi[j];
                float tdm = hd[j-1]; int tim = hi[j-1];
                hd[j]   = sw ? tdm : td;   hi[j]   = sw ? tim : ti;
                hd[j-1] = sw ? td  : tdm;  hi[j-1] = sw ? ti  : tim;
            }
        }
    }
    double sx=0, sy=0, sz=0, sxx=0, syy=0, szz=0, sxy=0, sxz=0, syz=0;
    #pragma unroll
    for (int k = 0; k < KN; k++) {
        int n = hi[k];
        float x = shp[n*3], y = shp[n*3+1], z = shp[n*3+2];
        g_grouped[(gc*KN + k)*3 + 0] = x;
        g_grouped[(gc*KN + k)*3 + 1] = y;
        g_grouped[(gc*KN + k)*3 + 2] = z;
        sx += x; sy += y; sz += z;
        sxx += (double)x*x; syy += (double)y*y; szz += (double)z*z;
        sxy += (double)x*y; sxz += (double)x*z; syz += (double)y*z;
    }
    atomicAdd(&s9[0], sx);  atomicAdd(&s9[1], sy);  atomicAdd(&s9[2], sz);
    atomicAdd(&s9[3], sxx); atomicAdd(&s9[4], syy); atomicAdd(&s9[5], szz);
    atomicAdd(&s9[6], sxy); atomicAdd(&s9[7], sxz); atomicAdd(&s9[8], syz);
    __syncthreads();
    if (t < 9) atomicAdd(&g_sum9[t], s9[t]);
}

// ---------------- BN1 affine from analytic moments ----------------
__global__ void bn1k(const float* __restrict__ b2, const float* __restrict__ g1,
                     const float* __restrict__ b1) {
    int o = threadIdx.x;
    if (o >= 256) return;
    double inv = 1.0 / (double)JJ;
    double Ex = g_sum9[0]*inv, Ey = g_sum9[1]*inv, Ez = g_sum9[2]*inv;
    double Mxx = g_sum9[3]*inv, Myy = g_sum9[4]*inv, Mzz = g_sum9[5]*inv;
    double Mxy = g_sum9[6]*inv, Mxz = g_sum9[7]*inv, Myz = g_sum9[8]*inv;
    double w0 = g_Weff2[o*3], w1v = g_Weff2[o*3+1], w2v = g_Weff2[o*3+2];
    double bo = b2[o];
    double wEg = w0*Ex + w1v*Ey + w2v*Ez;
    double m = wEg + bo;
    double Ex2 = w0*w0*Mxx + w1v*w1v*Myy + w2v*w2v*Mzz
               + 2.0*(w0*w1v*Mxy + w0*w2v*Mxz + w1v*w2v*Myz)
               + 2.0*bo*wEg + bo*bo;
    double var = Ex2 - m*m;
    double s = (double)g1[o] / sqrt(var + EPSf);
    g_A1[o*3+0] = (float)(s*w0);
    g_A1[o*3+1] = (float)(s*w1v);
    g_A1[o*3+2] = (float)(s*w2v);
    g_c1v[o] = (float)((double)b1[o] + s*(bo - m));
}

// ---------------- h generation + pooled ----------------
__global__ void hgenk() {
    __shared__ float gsh[48];
    int t = threadIdx.x;
    float a0 = g_A1[t*3], a1 = g_A1[t*3+1], a2 = g_A1[t*3+2], c1 = g_c1v[t];
    for (int it = 0; it < 8; it++) {
        int tile = blockIdx.x*8 + it;
        __syncthreads();
        if (t < 48) gsh[t] = g_grouped[tile*48 + t];
        __syncthreads();
        float hv[KN];
        float mx = 0.0f;
        #pragma unroll
        for (int k = 0; k < KN; k++) {
            float x = gsh[k*3], y = gsh[k*3+1], z = gsh[k*3+2];
            float h = fmaxf(0.0f, fmaf(a0, x, fmaf(a1, y, fmaf(a2, z, c1))));
            hv[k] = h;
            mx = fmaxf(mx, h);
        }
        float* dst = &g_H[(size_t)t*JJ + (size_t)tile*KN];
        #pragma unroll
        for (int q = 0; q < 4; q++)
            *(float4*)(dst + 4*q) = make_float4(hv[4*q], hv[4*q+1], hv[4*q+2], hv[4*q+3]);
        g_P[(size_t)t*NT + tile] = mx;
    }
}

// ---------------- generic 128x128 tiled GEMM, fused epilogues ----------------
// MODE 0: C = AT^T B                      (Zp)
// MODE 1: C = AT^T B + zp[o][j>>4], stats (Z, BN3)
// MODE 2: C = AT^T relu(a*B+d), stats     (Z4, BN4)
template<int MODE>
__global__ __launch_bounds__(256, 2)
void gemm128(const float* __restrict__ AT, int M,
             const float* __restrict__ Bm, int Nn,
             float* __restrict__ Cm, int Kdim,
             const float* __restrict__ zp,
             const float* __restrict__ ta, const float* __restrict__ tb,
             double* __restrict__ sumo, double* __restrict__ sqo) {
    __shared__ float As[2][8][128];
    __shared__ float Bs[2][8][128];
    __shared__ double shs[128], shq[128];
    int t = threadIdx.x;
    int tx = t & 15, ty = t >> 4;
    int o0 = blockIdx.y * 128, j0 = blockIdx.x * 128;
    int lk = t >> 5;            // 0..7
    int lo = (t & 31) * 4;      // 0..124

    float acc[8][8];
    #pragma unroll
    for (int r = 0; r < 8; r++)
        #pragma unroll
        for (int c = 0; c < 8; c++) acc[r][c] = 0.0f;

    // stage 0
    {
        float4 va = *(const float4*)&AT[(size_t)lk*M + o0 + lo];
        float4 vb = *(const float4*)&Bm[(size_t)lk*Nn + j0 + lo];
        if (MODE == 2) {
            float a = ta[lk], d = tb[lk];
            vb.x = fmaxf(0.0f, fmaf(vb.x, a, d));
            vb.y = fmaxf(0.0f, fmaf(vb.y, a, d));
            vb.z = fmaxf(0.0f, fmaf(vb.z, a, d));
            vb.w = fmaxf(0.0f, fmaf(vb.w, a, d));
        }
        *(float4*)&As[0][lk][lo] = va;
        *(float4*)&Bs[0][lk][lo] = vb;
    }
    __syncthreads();

    int cur = 0;
    for (int kc = 0; kc < Kdim; kc += 8) {
        bool has = (kc + 8) < Kdim;
        float4 ra, rb;
        if (has) {
            ra = *(const float4*)&AT[(size_t)(kc + 8 + lk)*M + o0 + lo];
            rb = *(const float4*)&Bm[(size_t)(kc + 8 + lk)*Nn + j0 + lo];
            if (MODE == 2) {
                float a = ta[kc + 8 + lk], d = tb[kc + 8 + lk];
                rb.x = fmaxf(0.0f, fmaf(rb.x, a, d));
                rb.y = fmaxf(0.0f, fmaf(rb.y, a, d));
                rb.z = fmaxf(0.0f, fmaf(rb.z, a, d));
                rb.w = fmaxf(0.0f, fmaf(rb.w, a, d));
            }
        }
        #pragma unroll
        for (int kk = 0; kk < 8; kk++) {
            float av[8], bv[8];
            *(float4*)&av[0] = *(float4*)&As[cur][kk][ty*8];
            *(float4*)&av[4] = *(float4*)&As[cur][kk][ty*8 + 4];
            *(float4*)&bv[0] = *(float4*)&Bs[cur][kk][tx*8];
            *(float4*)&bv[4] = *(float4*)&Bs[cur][kk][tx*8 + 4];
            #pragma unroll
            for (int r = 0; r < 8; r++)
                #pragma unroll
                for (int c = 0; c < 8; c++)
                    acc[r][c] = fmaf(av[r], bv[c], acc[r][c]);
        }
        if (has) {
            *(float4*)&As[cur^1][lk][lo] = ra;
            *(float4*)&Bs[cur^1][lk][lo] = rb;
        }
        __syncthreads();
        cur ^= 1;
    }

    if (MODE == 0) {
        #pragma unroll
        for (int r = 0; r < 8; r++) {
            int o = o0 + ty*8 + r;
            float* cp = &Cm[(size_t)o*Nn + j0 + tx*8];
            *(float4*)cp       = make_float4(acc[r][0], acc[r][1], acc[r][2], acc[r][3]);
            *(float4*)(cp + 4) = make_float4(acc[r][4], acc[r][5], acc[r][6], acc[r][7]);
        }
    } else {
        double rs[8], rq[8];
        #pragma unroll
        for (int r = 0; r < 8; r++) { rs[r] = 0.0; rq[r] = 0.0; }
        #pragma unroll
        for (int r = 0; r < 8; r++) {
            int o = o0 + ty*8 + r;
            float vals[8];
            #pragma unroll
            for (int c = 0; c < 8; c++) {
                int j = j0 + tx*8 + c;
                float v = acc[r][c];
                if (MODE == 1) v += zp[(size_t)o*NT + (j >> 4)];
                vals[c] = v;
                rs[r] += (double)v;
                rq[r] += (double)v * (double)v;
            }
            float* cp = &Cm[(size_t)o*Nn + j0 + tx*8];
            *(float4*)cp       = make_float4(vals[0], vals[1], vals[2], vals[3]);
            *(float4*)(cp + 4) = make_float4(vals[4], vals[5], vals[6], vals[7]);
        }
        if (t < 128) { shs[t] = 0.0; shq[t] = 0.0; }
        __syncthreads();
        #pragma unroll
        for (int r = 0; r < 8; r++) {
            atomicAdd(&shs[ty*8 + r], rs[r]);
            atomicAdd(&shq[ty*8 + r], rq[r]);
        }
        __syncthreads();
        if (t < 128) {
            atomicAdd(&sumo[o0 + t], shs[t]);
            atomicAdd(&sqo[o0 + t], shq[t]);
        }
    }
}

// ---------------- BN affine param kernels ----------------
__global__ void bn3aff(const float* __restrict__ g, const float* __restrict__ b) {
    int c = threadIdx.x;
    if (c >= 512) return;
    double inv = 1.0 / (double)JJ;
    double m = g_bn3sum[c]*inv;
    double var = g_bn3sq[c]*inv - m*m;
    float a = (float)((double)g[c] / sqrt(var + EPSf));
    g_a3[c] = a;
    g_d3[c] = b[c] - (float)m * a;
}
__global__ void bn4aff(const float* __restrict__ g, const float* __restrict__ b) {
    int c = threadIdx.x;
    if (c >= 256) return;
    double inv = 1.0 / (double)JJ;
    double m = g_bn4sum[c]*inv;
    double var = g_bn4sq[c]*inv - m*m;
    float a = (float)((double)g[c] / sqrt(var + EPSf));
    g_a4[c] = a;
    g_d4[c] = b[c] - (float)m * a;
}

// ---------------- final: BN4 + ReLU + max over k -> feat ----------------
__global__ void finalk(float* __restrict__ out) {
    int id = blockIdx.x*256 + threadIdx.x;            // b*131072 + o*512 + ns
    int b = id >> 17;
    int o = (id >> 9) & 255;
    int ns = id & 511;
    float a = g_a4[o], d = g_d4[o];
    const float4* zr = (const float4*)&g_Z4[(size_t)o*JJ + (size_t)((b << 9) | ns)*KN];
    float mx = 0.0f;
    #pragma unroll
    for (int q = 0; q < 4; q++) {
        float4 v = zr[q];
        mx = fmaxf(mx, fmaxf(0.0f, fmaf(v.x, a, d)));
        mx = fmaxf(mx, fmaxf(0.0f, fmaf(v.y, a, d)));
        mx = fmaxf(mx, fmaxf(0.0f, fmaf(v.z, a, d)));
        mx = fmaxf(mx, fmaxf(0.0f, fmaf(v.w, a, d)));
    }
    out[Bb*NSd*3 + id] = mx;
}

// ---------------- launch ----------------
extern "C" void kernel_launch(void* const* d_in, const int* in_sizes, int n_in,
                              void* d_out, int out_size) {
    const float* p    = (const float*)d_in[0];
    const float* w1   = (const float*)d_in[1];
    const float* w2   = (const float*)d_in[2];
    const float* b2   = (const float*)d_in[3];
    const float* bn1g = (const float*)d_in[4];
    const float* bn1b = (const float*)d_in[5];
    const float* w3   = (const float*)d_in[6];
    const float* bn3g = (const float*)d_in[7];
    const float* bn3b = (const float*)d_in[8];
    const float* w4   = (const float*)d_in[9];
    const float* bn4g = (const float*)d_in[10];
    const float* bn4b = (const float*)d_in[11];
    float* out = (float*)d_out;

    float*  dH;  cudaGetSymbolAddress((void**)&dH,  g_H);
    float*  dP;  cudaGetSymbolAddress((void**)&dP,  g_P);
    float*  dZp; cudaGetSymbolAddress((void**)&dZp, g_Zp);
    float*  dZ;  cudaGetSymbolAddress((void**)&dZ,  g_Z);
    float*  dZ4; cudaGetSymbolAddress((void**)&dZ4, g_Z4);
    float*  dW3T; cudaGetSymbolAddress((void**)&dW3T, g_W3T);
    float*  dW4T; cudaGetSymbolAddress((void**)&dW4T, g_W4T);
    float*  da3; cudaGetSymbolAddress((void**)&da3, g_a3);
    float*  dd3; cudaGetSymbolAddress((void**)&dd3, g_d3);
    double* ds3; cudaGetSymbolAddress((void**)&ds3, g_bn3sum);
    double* dq3; cudaGetSymbolAddress((void**)&dq3, g_bn3sq);
    double* ds4; cudaGetSymbolAddress((void**)&ds4, g_bn4sum);
    double* dq4; cudaGetSymbolAddress((void**)&dq4, g_bn4sq);

    zerok<<<1, 512>>>();
    precompk<<<1, 512>>>(w1, w2, w3, w4);
    fpsk<<<32, 512>>>(p, out);                 // writes cntrd to out[0:49152]
    knnk<<<64, 256>>>(p, out);
    bn1k<<<1, 256>>>(b2, bn1g, bn1b);
    hgenk<<<NT/8, 256>>>();
    // Zp = W3a @ pooled : M=512, K=256, N=16384
    gemm128<0><<<dim3(NT/128, 4), 256>>>(dW3T, 512, dP, NT, dZp, 256,
                                         nullptr, nullptr, nullptr, nullptr, nullptr);
    // Z = W3b @ H + zp, BN3 stats : M=512, K=256, N=262144
    gemm128<1><<<dim3(JJ/128, 4), 256>>>(dW3T + 256*512, 512, dH, JJ, dZ, 256,
                                         dZp, nullptr, nullptr, ds3, dq3);
    bn3aff<<<1, 512>>>(bn3g, bn3b);
    // Z4 = W4 @ relu(bn3(Z)), BN4 stats : M=256, K=512, N=262144
    gemm128<2><<<dim3(JJ/128, 2), 256>>>(dW4T, 256, dZ, JJ, dZ4, 512,
                                         nullptr, da3, dd3, ds4, dq4);
    bn4aff<<<1, 256>>>(bn4g, bn4b);
    finalk<<<Bb*256*NSd/256, 256>>>(out);
}